// round 1
// baseline (speedup 1.0000x reference)
#include <cuda_runtime.h>
#include <cstdint>

// Problem constants
#define NW        8192      // words
#define CL        16        // chars per word
#define CHID      128       // per-direction hidden
#define GATES     512       // 4*CHID
#define CDIM      64        // char embedding dim
#define WDIM      300       // word embedding dim
#define ODIM      512       // output dim
#define KPAD      576       // 556 padded to 9*64
#define KREAL     556

// ---------- device scratch (no cudaMalloc allowed) ----------
__device__ __align__(16) float g_P[2][128 * GATES];      // per-char gate preprojection (+bias)
__device__ __align__(16) float g_WhhT[2][CHID * GATES];  // Whh transposed [k][gate]
__device__ __align__(16) float g_WoutT[KPAD * ODIM];     // W_out transposed [d][o], zero-padded
__device__ __align__(16) float g_cf[NW * 256];           // summed bidir char features

// ---------- f32x2 helpers (Blackwell FFMA2: 2 IEEE fp32 FMA per issue) ----------
__device__ __forceinline__ unsigned long long dup2(float x) {
    unsigned long long r;
    asm("mov.b64 %0, {%1, %1};" : "=l"(r) : "f"(x));
    return r;
}
__device__ __forceinline__ unsigned long long pk2(float a, float b) {
    unsigned long long r;
    asm("mov.b64 %0, {%1, %2};" : "=l"(r) : "f"(a), "f"(b));
    return r;
}
__device__ __forceinline__ void upk2(unsigned long long v, float &a, float &b) {
    asm("mov.b64 {%0, %1}, %2;" : "=f"(a), "=f"(b) : "l"(v));
}
__device__ __forceinline__ void ffma2(unsigned long long &d, unsigned long long a,
                                      unsigned long long b) {
    asm("fma.rn.f32x2 %0, %1, %2, %0;" : "+l"(d) : "l"(a), "l"(b));
}

__device__ __forceinline__ float sigf(float x) {
    return __fdividef(1.0f, 1.0f + __expf(-x));
}
__device__ __forceinline__ float tanhf_fast(float x) {
    // tanh(x) = 2*sigmoid(2x)-1 ; __expf err ~2ulp -> abs err ~1e-6, far under 1e-3
    return 2.0f * __fdividef(1.0f, 1.0f + __expf(-2.0f * x)) - 1.0f;
}

// ---------- prep 1: P[dir][c][g] = char_table[c] . Wih[g] + bih[g] + bhh[g] ----------
__global__ void prep_P_kernel(const float *__restrict__ char_table,
                              const float *__restrict__ Wih_f, const float *__restrict__ bih_f,
                              const float *__restrict__ bhh_f,
                              const float *__restrict__ Wih_b, const float *__restrict__ bih_b,
                              const float *__restrict__ bhh_b) {
    int c = blockIdx.x, dir = blockIdx.y, tid = threadIdx.x;
    const float *Wih = dir ? Wih_b : Wih_f;
    const float *bi  = dir ? bih_b : bih_f;
    const float *bh  = dir ? bhh_b : bhh_f;
    __shared__ float cs[CDIM];
    if (tid < CDIM) cs[tid] = char_table[c * CDIM + tid];
    __syncthreads();
    for (int g = tid; g < GATES; g += blockDim.x) {
        float s = bi[g] + bh[g];
        const float *wr = Wih + g * CDIM;
#pragma unroll
        for (int d = 0; d < CDIM; ++d) s += cs[d] * wr[d];
        g_P[dir][c * GATES + g] = s;
    }
}

// ---------- prep 2: transposes (WhhT, WoutT with zero pad) ----------
__global__ void prep_T_kernel(const float *__restrict__ Whh_f,
                              const float *__restrict__ Whh_b,
                              const float *__restrict__ W_out) {
    int idx = blockIdx.x * blockDim.x + threadIdx.x;
    const int n_whh = 2 * CHID * GATES;  // 131072
    if (idx < n_whh) {
        int dir = idx >> 16;
        int r = idx & 65535;
        int k = r >> 9;       // 0..127
        int g = r & 511;
        const float *W = dir ? Whh_b : Whh_f;
        g_WhhT[dir][k * GATES + g] = W[g * CHID + k];
    } else {
        int j = idx - n_whh;
        if (j < KPAD * ODIM) {
            int d = j >> 9;   // 0..575
            int o = j & 511;
            g_WoutT[d * ODIM + o] = (d < KREAL) ? W_out[o * KREAL + d] : 0.0f;
        }
    }
}

// ---------- fused bidirectional char-LSTM ----------
// grid (128, 2): blockIdx.x -> 64-word tile, blockIdx.y -> direction.
// 512 threads: tid&15 -> word group (4 words), tid>>4 -> gate group (4 hidden j x 4 types).
// h kept in smem (transposed [j][word]); c and sum(h) in registers; WhhT staged in 64-row chunks.
#define LSTM_SMEM ((CHID * 64 + 64 * GATES) * 4 + 64 * CL * 4)

__global__ __launch_bounds__(512, 1) void lstm_kernel(const int *__restrict__ char_ids) {
    extern __shared__ float smem[];
    float *h_s = smem;                         // [128][64]
    float *w_s = smem + CHID * 64;             // [64][512]
    int *ci_s = (int *)(smem + CHID * 64 + 64 * GATES);  // [64][16]

    const int tid = threadIdx.x;
    const int dir = blockIdx.y;
    const int w_base = blockIdx.x * 64;
    const int wl0 = (tid & 15) * 4;   // local word base (0..60)
    const int j0 = (tid >> 4) * 4;    // hidden-j base (0..124)

    const float *Pd = g_P[dir];
    const float *WT = g_WhhT[dir];

    // stage char ids (contiguous [64 words][16])
    {
        const int *src = char_ids + (size_t)w_base * CL;
        ci_s[tid] = src[tid];
        ci_s[tid + 512] = src[tid + 512];
    }
    // zero h state
    {
        float4 *hz = (float4 *)h_s;
#pragma unroll
        for (int i = 0; i < 4; ++i) hz[tid + i * 512] = make_float4(0.f, 0.f, 0.f, 0.f);
    }
    float cst[4][4], hsum[4][4];
#pragma unroll
    for (int w = 0; w < 4; ++w)
#pragma unroll
        for (int j = 0; j < 4; ++j) { cst[w][j] = 0.f; hsum[w][j] = 0.f; }
    __syncthreads();

    unsigned long long acc2[4][8];  // [word][type*2 + pair]  (pair of consecutive j)

    for (int ti = 0; ti < CL; ++ti) {
        const int t = dir ? (CL - 1 - ti) : ti;

        // init gates from per-char preprojection (bias folded in)
#pragma unroll
        for (int w = 0; w < 4; ++w) {
            const int ch = ci_s[(wl0 + w) * CL + t];
            const float *Pr = Pd + ch * GATES;
#pragma unroll
            for (int ty = 0; ty < 4; ++ty) {
                float4 p = *(const float4 *)&Pr[ty * CHID + j0];
                acc2[w][ty * 2 + 0] = pk2(p.x, p.y);
                acc2[w][ty * 2 + 1] = pk2(p.z, p.w);
            }
        }

        // gates += h @ Whh^T, K staged in two 64-row chunks
#pragma unroll 1
        for (int kc = 0; kc < 2; ++kc) {
            __syncthreads();
            {
                const float4 *src = (const float4 *)(WT + kc * 64 * GATES);
                float4 *dst = (float4 *)w_s;
#pragma unroll
                for (int i = 0; i < 16; ++i) dst[tid + i * 512] = src[tid + i * 512];
            }
            __syncthreads();
#pragma unroll 4
            for (int k = 0; k < 64; ++k) {
                float4 h4 = *(const float4 *)&h_s[(kc * 64 + k) * 64 + wl0];
                unsigned long long hd0 = dup2(h4.x), hd1 = dup2(h4.y),
                                   hd2 = dup2(h4.z), hd3 = dup2(h4.w);
#pragma unroll
                for (int ty = 0; ty < 4; ++ty) {
                    ulonglong2 wv = *(const ulonglong2 *)&w_s[k * GATES + ty * CHID + j0];
                    ffma2(acc2[0][ty * 2 + 0], hd0, wv.x);
                    ffma2(acc2[0][ty * 2 + 1], hd0, wv.y);
                    ffma2(acc2[1][ty * 2 + 0], hd1, wv.x);
                    ffma2(acc2[1][ty * 2 + 1], hd1, wv.y);
                    ffma2(acc2[2][ty * 2 + 0], hd2, wv.x);
                    ffma2(acc2[2][ty * 2 + 1], hd2, wv.y);
                    ffma2(acc2[3][ty * 2 + 0], hd3, wv.x);
                    ffma2(acc2[3][ty * 2 + 1], hd3, wv.y);
                }
            }
        }
        __syncthreads();  // all h_s reads done before rewrite

        // pointwise LSTM cell + h sum + write h back (transposed)
#pragma unroll
        for (int w = 0; w < 4; ++w) {
            float ga[4][4];
#pragma unroll
            for (int ty = 0; ty < 4; ++ty) {
                upk2(acc2[w][ty * 2 + 0], ga[ty][0], ga[ty][1]);
                upk2(acc2[w][ty * 2 + 1], ga[ty][2], ga[ty][3]);
            }
#pragma unroll
            for (int jj = 0; jj < 4; ++jj) {
                float gi = sigf(ga[0][jj]);
                float gf = sigf(ga[1][jj]);
                float gg = tanhf_fast(ga[2][jj]);
                float go = sigf(ga[3][jj]);
                float cc = gf * cst[w][jj] + gi * gg;
                float hh = go * tanhf_fast(cc);
                cst[w][jj] = cc;
                hsum[w][jj] += hh;
                h_s[(j0 + jj) * 64 + wl0 + w] = hh;
            }
        }
    }

    // write summed features: cf[word][dir*128 + j]
#pragma unroll
    for (int w = 0; w < 4; ++w)
#pragma unroll
        for (int jj = 0; jj < 4; ++jj)
            g_cf[(size_t)(w_base + wl0 + w) * 256 + dir * CHID + j0 + jj] = hsum[w][jj];
}

// ---------- output GEMM: out = tanh([wordemb | cf] @ W_out^T + b_out) ----------
#define OUT_SMEM ((64 * 64 + 64 * ODIM) * 4 + 64 * 4)

__global__ __launch_bounds__(512, 1) void outgemm_kernel(const int *__restrict__ word_ids,
                                                         const float *__restrict__ word_table,
                                                         const float *__restrict__ b_out,
                                                         float *__restrict__ out) {
    extern __shared__ float smem[];
    float *feat_s = smem;                    // [64 k][64 w]
    float *w_s = smem + 64 * 64;             // [64 k][512 o]
    int *wid_s = (int *)(smem + 64 * 64 + 64 * ODIM);

    const int tid = threadIdx.x;
    const int w_base = blockIdx.x * 64;
    const int wl0 = (tid & 15) * 4;
    const int o0 = (tid >> 4) * 16;

    if (tid < 64) wid_s[tid] = word_ids[w_base + tid];
    __syncthreads();

    unsigned long long acc2[4][8];
#pragma unroll
    for (int w = 0; w < 4; ++w)
#pragma unroll
        for (int p = 0; p < 8; ++p) acc2[w][p] = 0ULL;

    const int wst = tid & 63;   // staging word
    const int kg = tid >> 6;    // staging k-group (8 k each)

#pragma unroll 1
    for (int kc = 0; kc < 9; ++kc) {
        __syncthreads();
        // stage feature chunk [64 k][64 w]
        {
            const int gw = w_base + wst;
            const int wid = wid_s[wst];
#pragma unroll
            for (int i = 0; i < 8; ++i) {
                int k = kg * 8 + i;
                int kk = kc * 64 + k;
                float v;
                if (kk < WDIM) v = word_table[(size_t)wid * WDIM + kk];
                else if (kk < KREAL) v = g_cf[(size_t)gw * 256 + (kk - WDIM)];
                else v = 0.0f;
                feat_s[k * 64 + wst] = v;
            }
        }
        // stage W chunk
        {
            const float4 *src = (const float4 *)(g_WoutT + kc * 64 * ODIM);
            float4 *dst = (float4 *)w_s;
#pragma unroll
            for (int i = 0; i < 16; ++i) dst[tid + i * 512] = src[tid + i * 512];
        }
        __syncthreads();
#pragma unroll 4
        for (int k = 0; k < 64; ++k) {
            float4 h4 = *(const float4 *)&feat_s[k * 64 + wl0];
            unsigned long long hd0 = dup2(h4.x), hd1 = dup2(h4.y),
                               hd2 = dup2(h4.z), hd3 = dup2(h4.w);
#pragma unroll
            for (int q = 0; q < 4; ++q) {
                ulonglong2 wv = *(const ulonglong2 *)&w_s[k * ODIM + o0 + q * 4];
                ffma2(acc2[0][q * 2 + 0], hd0, wv.x);
                ffma2(acc2[0][q * 2 + 1], hd0, wv.y);
                ffma2(acc2[1][q * 2 + 0], hd1, wv.x);
                ffma2(acc2[1][q * 2 + 1], hd1, wv.y);
                ffma2(acc2[2][q * 2 + 0], hd2, wv.x);
                ffma2(acc2[2][q * 2 + 1], hd2, wv.y);
                ffma2(acc2[3][q * 2 + 0], hd3, wv.x);
                ffma2(acc2[3][q * 2 + 1], hd3, wv.y);
            }
        }
    }

    // epilogue: bias + tanh + store
#pragma unroll
    for (int w = 0; w < 4; ++w) {
        const size_t row = (size_t)(w_base + wl0 + w) * ODIM;
#pragma unroll
        for (int q = 0; q < 4; ++q) {
            float v0, v1, v2, v3;
            upk2(acc2[w][q * 2 + 0], v0, v1);
            upk2(acc2[w][q * 2 + 1], v2, v3);
            float4 bo = *(const float4 *)&b_out[o0 + q * 4];
            float4 r;
            r.x = tanhf_fast(v0 + bo.x);
            r.y = tanhf_fast(v1 + bo.y);
            r.z = tanhf_fast(v2 + bo.z);
            r.w = tanhf_fast(v3 + bo.w);
            *(float4 *)&out[row + o0 + q * 4] = r;
        }
    }
}

// ---------- launch ----------
extern "C" void kernel_launch(void *const *d_in, const int *in_sizes, int n_in,
                              void *d_out, int out_size) {
    const int *word_ids     = (const int *)d_in[0];
    const int *char_ids     = (const int *)d_in[1];
    const float *word_table = (const float *)d_in[2];
    const float *char_table = (const float *)d_in[3];
    const float *Wih_f = (const float *)d_in[4];
    const float *Whh_f = (const float *)d_in[5];
    const float *bih_f = (const float *)d_in[6];
    const float *bhh_f = (const float *)d_in[7];
    const float *Wih_b = (const float *)d_in[8];
    const float *Whh_b = (const float *)d_in[9];
    const float *bih_b = (const float *)d_in[10];
    const float *bhh_b = (const float *)d_in[11];
    const float *W_out = (const float *)d_in[12];
    const float *b_out = (const float *)d_in[13];
    float *out = (float *)d_out;

    cudaFuncSetAttribute(lstm_kernel, cudaFuncAttributeMaxDynamicSharedMemorySize, LSTM_SMEM);
    cudaFuncSetAttribute(outgemm_kernel, cudaFuncAttributeMaxDynamicSharedMemorySize, OUT_SMEM);

    prep_P_kernel<<<dim3(128, 2), 128>>>(char_table, Wih_f, bih_f, bhh_f,
                                         Wih_b, bih_b, bhh_b);
    {
        const int total = 2 * CHID * GATES + KPAD * ODIM;  // 131072 + 294912
        prep_T_kernel<<<(total + 255) / 256, 256>>>(Whh_f, Whh_b, W_out);
    }
    lstm_kernel<<<dim3(128, 2), 512, LSTM_SMEM>>>(char_ids);
    outgemm_kernel<<<128, 512, OUT_SMEM>>>(word_ids, word_table, b_out, out);
}